// round 15
// baseline (speedup 1.0000x reference)
#include <cuda_runtime.h>
#include <cuda_fp16.h>
#include <cstdint>

// ---------------- problem constants ----------------
#define B_      32
#define L_      32768
#define KW      16
#define D_      128
#define STRIDE_ 8
#define P_      4095
#define NCH     16           // K chunks (32 fp32 each, total 512)
#define NTILES  512          // 16 p-tiles x 32 batches

// ---------------- smem layout (bytes) ----------------
// Full B resident: 16 chunks x 8KB = 128KB @0.
// A: 4 pairs x 2 bufs x 4KB = 32KB @128KB.  smed(256f), cb(128f) after.
#define OFF_B    0
#define OFF_A    131072
#define OFF_SMED 163840
#define OFF_CB   164864
#define SM_TOTAL 165376

#define SWZ(a) ((a) ^ (((a) >> 3) & 0x70))

// ---------------- precomputed W fragments (fp16), 128KB ----------------
// layout: [chunk(16)][ks(2)][ntp(8)][lane(32)][4 u32] (u32 = fp16x2)
// natural k-order: b0 regs: m = ks*16 + 2t + {0,1}; b1 regs: m = ks*16 + 2t+8 + {0,1}
__device__ uint32_t g_Bh[NCH * 2048];

__global__ void prep_w_kernel(const float* __restrict__ w) {
    int idx = blockIdx.x * 256 + threadIdx.x;       // 0..32767
    int r    = idx & 3;          // {nt0.b0, nt0.b1, nt1.b0, nt1.b1}
    int lane = (idx >> 2) & 31;
    int ntp  = (idx >> 7) & 7;
    int ks   = (idx >> 10) & 1;
    int ci   = idx >> 11;        // chunk = conv tap k
    int nt   = ntp * 2 + (r >> 1);
    int breg = r & 1;
    int n = nt * 8 + (lane >> 2);                   // d row
    int t = lane & 3;
    int m0 = ks * 16 + 2 * t + 8 * breg;
    float v0 = w[n * 512 + m0 * 16 + ci];
    float v1 = w[n * 512 + (m0 + 1) * 16 + ci];
    __half2 h = __floats2half2_rn(v0, v1);
    g_Bh[idx] = *(uint32_t*)&h;
}

// ---------------- wrappers ----------------
__device__ __forceinline__ void mma_f16(float* c, uint4 a, uint32_t b0, uint32_t b1) {
    asm volatile(
        "mma.sync.aligned.m16n8k16.row.col.f32.f16.f16.f32 "
        "{%0,%1,%2,%3}, {%4,%5,%6,%7}, {%8,%9}, {%0,%1,%2,%3};"
        : "+f"(c[0]), "+f"(c[1]), "+f"(c[2]), "+f"(c[3])
        : "r"(a.x), "r"(a.y), "r"(a.z), "r"(a.w), "r"(b0), "r"(b1));
}

__device__ __forceinline__ uint4 ldsm4(uint32_t addr) {
    uint4 v;
    asm volatile("ldmatrix.sync.aligned.m8n8.x4.shared.b16 {%0,%1,%2,%3}, [%4];"
                 : "=r"(v.x), "=r"(v.y), "=r"(v.z), "=r"(v.w) : "r"(addr));
    return v;
}

__device__ __forceinline__ uint32_t smem_u32(const void* p) {
    uint32_t a;
    asm("{ .reg .u64 t; cvta.to.shared.u64 t, %1; cvt.u32.u64 %0, t; }" : "=r"(a) : "l"(p));
    return a;
}

// ---------------- main kernel: persistent CTAs (grid = #SMs) ----------------
__global__ __launch_bounds__(256, 1)
void encoder_hmma_kernel(const float* __restrict__ x,
                         const float* __restrict__ ts,
                         const float* __restrict__ bias,
                         float* __restrict__ out) {
    extern __shared__ char smem[];
    const int tid  = threadIdx.x;
    const int lane = tid & 31;
    const int wid  = tid >> 5;     // 0..7
    const int wm   = wid >> 1;     // 0..3  (64 p rows each)
    const int wn   = wid & 1;      // 0..1  (64 d cols each)
    const int t    = lane & 3;
    const int g    = lane >> 2;

    float* smed = (float*)(smem + OFF_SMED);
    float* cb   = (float*)(smem + OFF_CB);

    const uint32_t smemB = smem_u32(smem) + OFF_B;
    const uint32_t smemA = smem_u32(smem) + OFF_A + wm * 8192;   // pair-private

    // ---- fill ALL of B once per CTA (128KB; 512B per thread) ----
    {
        uint32_t dst = smemB + tid * 16;
        const uint4* srcp = (const uint4*)g_Bh + tid;
        #pragma unroll
        for (int i = 0; i < 32; i++) {
            asm volatile("cp.async.ca.shared.global [%0], [%1], 16;"
                         :: "r"(dst + i * 4096), "l"(srcp + i * 256));
        }
        asm volatile("cp.async.commit_group;");
    }
    if (tid < 128) cb[tid] = bias[tid];

    // epilogue constants (tile-invariant)
    float dt[8];
    #pragma unroll
    for (int nt = 0; nt < 8; nt++) {
        int i = wn * 32 + nt * 4 + t;                // d0/2
        dt[nt] = __expf((float)i * -0.14391156831f); // -2*ln(10000)/128
    }

    // LDSM source offsets (local rows 0..63; tile-invariant)
    uint32_t lds_off[2][4];
    {
        int row_l = (lane & 7) + (lane & 8);
        int cbyt  = (lane >> 4) << 4;
        #pragma unroll
        for (int ks = 0; ks < 2; ks++)
            #pragma unroll
            for (int mt = 0; mt < 4; mt++)
                lds_off[ks][mt] = SWZ((uint32_t)((row_l + mt * 16) * 64 + cbyt + ks * 32));
    }
    const int pt  = tid & 63;
    const int r0p = pt >> 3;
    const int j   = pt & 7;
    const uint32_t sts_base = (uint32_t)(r0p * 64 + (j >> 1) * 16);
    const uint32_t sts_lo   = (uint32_t)((j & 1) * 8);

    asm volatile("cp.async.wait_group 0;" ::: "memory");
    __syncthreads();     // B + cb visible for the whole kernel

    const uint4* Bs = (const uint4*)(smem + OFF_B);

    // ---- persistent tile loop ----
    for (int tile = blockIdx.x; tile < NTILES; tile += gridDim.x) {
        const int b  = tile & 31;
        const int p0 = (tile >> 5) * 256;
        const char*  xbc = (const char*)(x + (size_t)b * (L_ * 32));

        // medians for this tile (one p-row per thread)
        {
            int p = p0 + tid;
            float med = 0.f;
            if (p < P_) {
                float v[KW];
                const float* tp = ts + b * L_ + p * STRIDE_;
                #pragma unroll
                for (int i = 0; i < KW; i++) v[i] = tp[i];
                #pragma unroll
                for (int pass = 0; pass < KW; pass++) {
                    int st = pass & 1;
                    #pragma unroll
                    for (int i = 0; i < KW - 1; i++) {
                        if ((i & 1) == st) {
                            float lo = fminf(v[i], v[i + 1]);
                            float hi = fmaxf(v[i], v[i + 1]);
                            v[i] = lo; v[i + 1] = hi;
                        }
                    }
                }
                med = v[(KW - 1) / 2];
            }
            smed[tid] = med;
        }

        // A gmem offsets for this tile
        uint32_t offA[8];
        #pragma unroll
        for (int i = 0; i < 8; i++) {
            int p = p0 + wm * 64 + r0p + 8 * i;
            offA[i] = (p < P_) ? ((uint32_t)p * 1024u + (uint32_t)j * 16u)
                               : ((uint32_t)j * 16u);
        }

        float4 xa[8];
        #define LOAD_X(CI) do {                                               \
            _Pragma("unroll")                                                 \
            for (int i = 0; i < 8; i++)                                       \
                xa[i] = *(const float4*)(xbc + offA[i] + (CI) * 128);         \
        } while (0)

        #define STS_A(BUF) do {                                               \
            uint32_t sb = smemA + (BUF) * 4096;                               \
            _Pragma("unroll")                                                 \
            for (int i = 0; i < 8; i++) {                                     \
                __half2 h0 = __floats2half2_rn(xa[i].x, xa[i].y);             \
                __half2 h1 = __floats2half2_rn(xa[i].z, xa[i].w);             \
                uint32_t ad = SWZ(sts_base + (uint32_t)(i * 512)) + sts_lo;   \
                asm volatile("st.shared.v2.b32 [%0], {%1, %2};"               \
                    :: "r"(sb + ad), "r"(*(uint32_t*)&h0), "r"(*(uint32_t*)&h1)); \
            }                                                                 \
        } while (0)

        #define BARP() asm volatile("bar.sync %0, 64;" :: "r"(wm + 1) : "memory")

        #define COMPUTE(BUF, CI) do {                                         \
            uint32_t abase = smemA + (BUF) * 4096;                            \
            _Pragma("unroll")                                                 \
            for (int ks = 0; ks < 2; ks++) {                                  \
                uint4 af[4];                                                  \
                _Pragma("unroll")                                             \
                for (int mt = 0; mt < 4; mt++) af[mt] = ldsm4(abase + lds_off[ks][mt]); \
                const uint4* brow = Bs + ((CI) * 2 + ks) * 256 + wn * 128 + lane; \
                uint4 bb0 = brow[0];                                          \
                uint4 bb1 = brow[32];                                         \
                uint4 bb2 = brow[64];                                         \
                uint4 bb3 = brow[96];                                         \
                _Pragma("unroll")                                             \
                for (int mt = 0; mt < 4; mt++) {                              \
                    mma_f16(acc[mt][0], af[mt], bb0.x, bb0.y);                \
                    mma_f16(acc[mt][1], af[mt], bb0.z, bb0.w);                \
                    mma_f16(acc[mt][2], af[mt], bb1.x, bb1.y);                \
                    mma_f16(acc[mt][3], af[mt], bb1.z, bb1.w);                \
                    mma_f16(acc[mt][4], af[mt], bb2.x, bb2.y);                \
                    mma_f16(acc[mt][5], af[mt], bb2.z, bb2.w);                \
                    mma_f16(acc[mt][6], af[mt], bb3.x, bb3.y);                \
                    mma_f16(acc[mt][7], af[mt], bb3.z, bb3.w);                \
                }                                                             \
            }                                                                 \
        } while (0)

        float acc[4][8][4];
        #pragma unroll
        for (int i = 0; i < 4; i++)
            #pragma unroll
            for (int jj = 0; jj < 8; jj++)
                #pragma unroll
                for (int q = 0; q < 4; q++) acc[i][jj][q] = 0.f;

        // prologue staging for this tile
        LOAD_X(0);
        STS_A(0);
        LOAD_X(1);
        STS_A(1);
        LOAD_X(2);
        __syncthreads();     // smed + A bufs visible CTA-wide

        // main loop: pair barriers only; tail BARP closes the staging race
        #pragma unroll 2
        for (int ci = 0; ci < NCH; ci++) {
            COMPUTE(ci & 1, ci);
            if (ci + 2 < NCH) {
                BARP();                        // pair done reading buf (ci&1)
                STS_A(ci & 1);                 // stage chunk ci+2
                if (ci + 3 < NCH) LOAD_X(ci + 3);
            } else if (ci + 2 == NCH) {
                BARP();                        // order partner's last STS_A
            }
        }

        // epilogue: bias + sinusoidal PE from median
        #pragma unroll
        for (int mt = 0; mt < 4; mt++) {
            #pragma unroll
            for (int half = 0; half < 2; half++) {
                int prow = wm * 64 + mt * 16 + g + half * 8;
                int p = p0 + prow;
                if (p >= P_) continue;
                float med = smed[prow];
                float* orow = out + ((size_t)b * P_ + p) * D_;
                #pragma unroll
                for (int nt = 0; nt < 8; nt++) {
                    int d0 = wn * 64 + nt * 8 + 2 * t;
                    float sn, cs;
                    __sincosf(med * dt[nt], &sn, &cs);
                    float2 o;
                    o.x = acc[mt][nt][half * 2 + 0] + cb[d0] + sn;
                    o.y = acc[mt][nt][half * 2 + 1] + cb[d0 + 1] + cs;
                    *(float2*)(orow + d0) = o;
                }
            }
        }
        __syncthreads();     // done reading smed/A before next tile overwrites
    }
}

extern "C" void kernel_launch(void* const* d_in, const int* in_sizes, int n_in,
                              void* d_out, int out_size) {
    const float* x    = (const float*)d_in[0];
    const float* ts   = (const float*)d_in[1];
    const float* w    = (const float*)d_in[2];
    const float* bias = (const float*)d_in[3];
    float* out = (float*)d_out;

    prep_w_kernel<<<128, 256>>>(w);

    int nsm = 0;
    cudaDeviceGetAttribute(&nsm, cudaDevAttrMultiProcessorCount, 0);
    if (nsm <= 0) nsm = 148;

    cudaFuncSetAttribute(encoder_hmma_kernel,
                         cudaFuncAttributeMaxDynamicSharedMemorySize, SM_TOTAL);
    encoder_hmma_kernel<<<nsm, 256, SM_TOTAL>>>(x, ts, bias, out);
}

// round 16
// speedup vs baseline: 1.0355x; 1.0355x over previous
#include <cuda_runtime.h>
#include <cuda_fp16.h>
#include <cstdint>

// ---------------- problem constants ----------------
#define B_      32
#define L_      32768
#define KW      16
#define D_      128
#define STRIDE_ 8
#define P_      4095
#define NCH     16           // K chunks (32 fp32 each, total 512)

// ---------------- smem layout (bytes) ----------------
// Full B resident: 16 chunks x 8KB = 128KB @0.
// A: 4 pairs x 3 bufs x 4KB = 48KB @128KB.  smed(256f), cb(128f) after.
#define OFF_B    0
#define OFF_A    131072
#define OFF_SMED 180224
#define OFF_CB   181248
#define SM_TOTAL 181760

#define SWZ(a) ((a) ^ (((a) >> 3) & 0x70))

// ---------------- precomputed W fragments (fp16), 128KB ----------------
// layout: [chunk(16)][ks(2)][ntp(8)][lane(32)][4 u32] (u32 = fp16x2)
// natural k-order: b0 regs: m = ks*16 + 2t + {0,1}; b1 regs: m = ks*16 + 2t+8 + {0,1}
__device__ uint32_t g_Bh[NCH * 2048];

__global__ void prep_w_kernel(const float* __restrict__ w) {
    int idx = blockIdx.x * 256 + threadIdx.x;       // 0..32767
    int r    = idx & 3;          // {nt0.b0, nt0.b1, nt1.b0, nt1.b1}
    int lane = (idx >> 2) & 31;
    int ntp  = (idx >> 7) & 7;
    int ks   = (idx >> 10) & 1;
    int ci   = idx >> 11;        // chunk = conv tap k
    int nt   = ntp * 2 + (r >> 1);
    int breg = r & 1;
    int n = nt * 8 + (lane >> 2);                   // d row
    int t = lane & 3;
    int m0 = ks * 16 + 2 * t + 8 * breg;
    float v0 = w[n * 512 + m0 * 16 + ci];
    float v1 = w[n * 512 + (m0 + 1) * 16 + ci];
    __half2 h = __floats2half2_rn(v0, v1);
    g_Bh[idx] = *(uint32_t*)&h;
}

// ---------------- wrappers ----------------
__device__ __forceinline__ void mma_f16(float* c, uint4 a, uint32_t b0, uint32_t b1) {
    asm volatile(
        "mma.sync.aligned.m16n8k16.row.col.f32.f16.f16.f32 "
        "{%0,%1,%2,%3}, {%4,%5,%6,%7}, {%8,%9}, {%0,%1,%2,%3};"
        : "+f"(c[0]), "+f"(c[1]), "+f"(c[2]), "+f"(c[3])
        : "r"(a.x), "r"(a.y), "r"(a.z), "r"(a.w), "r"(b0), "r"(b1));
}

__device__ __forceinline__ uint4 ldsm4(uint32_t addr) {
    uint4 v;
    asm volatile("ldmatrix.sync.aligned.m8n8.x4.shared.b16 {%0,%1,%2,%3}, [%4];"
                 : "=r"(v.x), "=r"(v.y), "=r"(v.z), "=r"(v.w) : "r"(addr));
    return v;
}

__device__ __forceinline__ uint32_t smem_u32(const void* p) {
    uint32_t a;
    asm("{ .reg .u64 t; cvta.to.shared.u64 t, %1; cvt.u32.u64 %0, t; }" : "=r"(a) : "l"(p));
    return a;
}

// ---------------- main kernel: 256 thr, 4x2 warps of 64p x 64d, 1 CTA/SM ----------------
__global__ __launch_bounds__(256, 1)
void encoder_hmma_kernel(const float* __restrict__ x,
                         const float* __restrict__ ts,
                         const float* __restrict__ bias,
                         float* __restrict__ out) {
    extern __shared__ char smem[];
    const int tid  = threadIdx.x;
    const int lane = tid & 31;
    const int wid  = tid >> 5;     // 0..7
    const int wm   = wid >> 1;     // 0..3  (64 p rows each)
    const int wn   = wid & 1;      // 0..1  (64 d cols each)
    const int t    = lane & 3;
    const int g    = lane >> 2;
    const int p0   = blockIdx.x * 256;
    const int b    = blockIdx.y;

    float* smed = (float*)(smem + OFF_SMED);
    float* cb   = (float*)(smem + OFF_CB);
    const char* xbc = (const char*)(x + (size_t)b * (L_ * 32));

    const uint32_t smemB = smem_u32(smem) + OFF_B;
    const uint32_t smemA = smem_u32(smem) + OFF_A + wm * 12288;   // pair-private, 3 bufs

    // ---- fill ALL of B once (128KB; 512B per thread) ----
    {
        uint32_t dst = smemB + tid * 16;
        const uint4* srcp = (const uint4*)g_Bh + tid;
        #pragma unroll
        for (int i = 0; i < 32; i++) {
            asm volatile("cp.async.ca.shared.global [%0], [%1], 16;"
                         :: "r"(dst + i * 4096), "l"(srcp + i * 256));
        }
        asm volatile("cp.async.commit_group;");
    }

    // ---- bias + medians (one p-row per thread, 256 rows) ----
    {
        if (tid < 128) cb[tid] = bias[tid];
        int p = p0 + tid;
        float med = 0.f;
        if (p < P_) {
            float v[KW];
            const float* tp = ts + b * L_ + p * STRIDE_;
            #pragma unroll
            for (int i = 0; i < KW; i++) v[i] = tp[i];
            #pragma unroll
            for (int pass = 0; pass < KW; pass++) {
                int st = pass & 1;
                #pragma unroll
                for (int i = 0; i < KW - 1; i++) {
                    if ((i & 1) == st) {
                        float lo = fminf(v[i], v[i + 1]);
                        float hi = fmaxf(v[i], v[i + 1]);
                        v[i] = lo; v[i + 1] = hi;
                    }
                }
            }
            med = v[(KW - 1) / 2];
        }
        smed[tid] = med;
    }

    // ---- A staging addressing (pair-local) ----
    const int pt  = tid & 63;
    const int r0p = pt >> 3;
    const int j   = pt & 7;
    uint32_t offA[8];     // byte offset into xbc (chunk adds ci*128)
    #pragma unroll
    for (int i = 0; i < 8; i++) {
        int p = p0 + wm * 64 + r0p + 8 * i;
        offA[i] = (p < P_) ? ((uint32_t)p * 1024u + (uint32_t)j * 16u) : ((uint32_t)j * 16u);
    }
    const uint32_t sts_base = (uint32_t)(r0p * 64 + (j >> 1) * 16);
    const uint32_t sts_lo   = (uint32_t)((j & 1) * 8);

    // ---- LDSM source offsets (local rows 0..63) ----
    uint32_t lds_off[2][4];
    {
        int row_l = (lane & 7) + (lane & 8);
        int cbyt  = (lane >> 4) << 4;
        #pragma unroll
        for (int ks = 0; ks < 2; ks++)
            #pragma unroll
            for (int mt = 0; mt < 4; mt++)
                lds_off[ks][mt] = SWZ((uint32_t)((row_l + mt * 16) * 64 + cbyt + ks * 32));
    }

    float4 xa[8];
    #define LOAD_X(CI) do {                                                   \
        _Pragma("unroll")                                                     \
        for (int i = 0; i < 8; i++)                                           \
            xa[i] = *(const float4*)(xbc + offA[i] + (CI) * 128);             \
    } while (0)

    #define STS_A(BUF) do {                                                   \
        uint32_t sb = smemA + (BUF) * 4096;                                   \
        _Pragma("unroll")                                                     \
        for (int i = 0; i < 8; i++) {                                         \
            __half2 h0 = __floats2half2_rn(xa[i].x, xa[i].y);                 \
            __half2 h1 = __floats2half2_rn(xa[i].z, xa[i].w);                 \
            uint32_t ad = SWZ(sts_base + (uint32_t)(i * 512)) + sts_lo;       \
            asm volatile("st.shared.v2.b32 [%0], {%1, %2};"                   \
                :: "r"(sb + ad), "r"(*(uint32_t*)&h0), "r"(*(uint32_t*)&h1)); \
        }                                                                     \
    } while (0)

    // pair barrier: 2 warps (64 threads), id = wm+1
    #define BARP() asm volatile("bar.sync %0, 64;" :: "r"(wm + 1) : "memory")

    float acc[4][8][4];
    #pragma unroll
    for (int i = 0; i < 4; i++)
        #pragma unroll
        for (int jj = 0; jj < 8; jj++)
            #pragma unroll
            for (int q = 0; q < 4; q++) acc[i][jj][q] = 0.f;

    const uint4* Bs = (const uint4*)(smem + OFF_B);

    // B loads issued first so their latency hides under LDSM issue
    #define COMPUTE(BUF, CI) do {                                             \
        uint32_t abase = smemA + (BUF) * 4096;                                \
        _Pragma("unroll")                                                     \
        for (int ks = 0; ks < 2; ks++) {                                      \
            const uint4* brow = Bs + ((CI) * 2 + ks) * 256 + wn * 128 + lane; \
            uint4 bb0 = brow[0];                                              \
            uint4 bb1 = brow[32];                                             \
            uint4 bb2 = brow[64];                                             \
            uint4 bb3 = brow[96];                                             \
            uint4 af[4];                                                      \
            _Pragma("unroll")                                                 \
            for (int mt = 0; mt < 4; mt++) af[mt] = ldsm4(abase + lds_off[ks][mt]); \
            _Pragma("unroll")                                                 \
            for (int mt = 0; mt < 4; mt++) {                                  \
                mma_f16(acc[mt][0], af[mt], bb0.x, bb0.y);                    \
                mma_f16(acc[mt][1], af[mt], bb0.z, bb0.w);                    \
                mma_f16(acc[mt][2], af[mt], bb1.x, bb1.y);                    \
                mma_f16(acc[mt][3], af[mt], bb1.z, bb1.w);                    \
                mma_f16(acc[mt][4], af[mt], bb2.x, bb2.y);                    \
                mma_f16(acc[mt][5], af[mt], bb2.z, bb2.w);                    \
                mma_f16(acc[mt][6], af[mt], bb3.x, bb3.y);                    \
                mma_f16(acc[mt][7], af[mt], bb3.z, bb3.w);                    \
            }                                                                 \
        }                                                                     \
    } while (0)

    // ---- prologue: stage chunks 0,1 into bufs 0,1; chunk 2 in regs ----
    LOAD_X(0);
    STS_A(0);
    LOAD_X(1);
    STS_A(1);
    LOAD_X(2);
    asm volatile("cp.async.wait_group 0;" ::: "memory");
    __syncthreads();     // B + A bufs + medians visible (ONLY CTA-wide sync)

    // ---- main loop: 3-buf A ring; BARP gives 1-chunk pair slack ----
    // write at iter ci targets buf (ci+2)%3 == buf of chunk ci-1 (already consumed);
    // read of chunk ci protected by partner's BARP at iter ci-1.
    #pragma unroll 2
    for (int ci = 0; ci < NCH; ci++) {
        const int rbuf = ci % 3;
        COMPUTE(rbuf, ci);
        if (ci + 2 < NCH) {
            BARP();                        // both warps past COMPUTE(ci)
            STS_A((ci + 2) % 3);           // stage chunk ci+2
            if (ci + 3 < NCH) LOAD_X(ci + 3);
        } else if (ci + 2 == NCH) {
            BARP();                        // order partner's last STS_A
        }
    }

    // ---- epilogue: bias + sinusoidal PE from median ----
    {
        float dt[8];
        #pragma unroll
        for (int nt = 0; nt < 8; nt++) {
            int i = wn * 32 + nt * 4 + t;                // d0/2
            dt[nt] = __expf((float)i * -0.14391156831f); // -2*ln(10000)/128
        }
        #pragma unroll
        for (int mt = 0; mt < 4; mt++) {
            #pragma unroll
            for (int half = 0; half < 2; half++) {
                int prow = wm * 64 + mt * 16 + g + half * 8;
                int p = p0 + prow;
                if (p >= P_) continue;
                float med = smed[prow];
                float* orow = out + ((size_t)b * P_ + p) * D_;
                #pragma unroll
                for (int nt = 0; nt < 8; nt++) {
                    int d0 = wn * 64 + nt * 8 + 2 * t;
                    float sn, cs;
                    __sincosf(med * dt[nt], &sn, &cs);
                    float2 o;
                    o.x = acc[mt][nt][half * 2 + 0] + cb[d0] + sn;
                    o.y = acc[mt][nt][half * 2 + 1] + cb[d0 + 1] + cs;
                    *(float2*)(orow + d0) = o;
                }
            }
        }
    }
}

extern "C" void kernel_launch(void* const* d_in, const int* in_sizes, int n_in,
                              void* d_out, int out_size) {
    const float* x    = (const float*)d_in[0];
    const float* ts   = (const float*)d_in[1];
    const float* w    = (const float*)d_in[2];
    const float* bias = (const float*)d_in[3];
    float* out = (float*)d_out;

    prep_w_kernel<<<128, 256>>>(w);

    cudaFuncSetAttribute(encoder_hmma_kernel,
                         cudaFuncAttributeMaxDynamicSharedMemorySize, SM_TOTAL);
    dim3 grid(16, B_);
    encoder_hmma_kernel<<<grid, 256, SM_TOTAL>>>(x, ts, bias, out);
}

// round 17
// speedup vs baseline: 1.0633x; 1.0268x over previous
#include <cuda_runtime.h>
#include <cuda_fp16.h>
#include <cstdint>

// ---------------- problem constants ----------------
#define B_      32
#define L_      32768
#define KW      16
#define D_      128
#define STRIDE_ 8
#define P_      4095
#define NCH     16           // K chunks (32 fp32 each, total 512)

// ---------------- smem layout (bytes) ----------------
// Full B resident: 16 chunks x 8KB = 128KB @0.
// A: 4 groups x 2 bufs x 4KB = 32KB @128KB.  smed(256f), cb(128f) after.
#define OFF_B    0
#define OFF_A    131072
#define OFF_SMED 163840
#define OFF_CB   164864
#define SM_TOTAL 165376

#define SWZ(a) ((a) ^ (((a) >> 3) & 0x70))

// ---------------- precomputed W fragments (fp16), 128KB ----------------
// layout: [chunk(16)][ks(2)][ntp(8)][lane(32)][4 u32] (u32 = fp16x2)
// natural k-order: b0 regs: m = ks*16 + 2t + {0,1}; b1 regs: m = ks*16 + 2t+8 + {0,1}
__device__ uint32_t g_Bh[NCH * 2048];

__global__ void prep_w_kernel(const float* __restrict__ w) {
    int idx = blockIdx.x * 256 + threadIdx.x;       // 0..32767
    int r    = idx & 3;          // {nt0.b0, nt0.b1, nt1.b0, nt1.b1}
    int lane = (idx >> 2) & 31;
    int ntp  = (idx >> 7) & 7;
    int ks   = (idx >> 10) & 1;
    int ci   = idx >> 11;        // chunk = conv tap k
    int nt   = ntp * 2 + (r >> 1);
    int breg = r & 1;
    int n = nt * 8 + (lane >> 2);                   // d row
    int t = lane & 3;
    int m0 = ks * 16 + 2 * t + 8 * breg;
    float v0 = w[n * 512 + m0 * 16 + ci];
    float v1 = w[n * 512 + (m0 + 1) * 16 + ci];
    __half2 h = __floats2half2_rn(v0, v1);
    g_Bh[idx] = *(uint32_t*)&h;
}

// ---------------- wrappers ----------------
__device__ __forceinline__ void mma_f16(float* c, uint4 a, uint32_t b0, uint32_t b1) {
    asm volatile(
        "mma.sync.aligned.m16n8k16.row.col.f32.f16.f16.f32 "
        "{%0,%1,%2,%3}, {%4,%5,%6,%7}, {%8,%9}, {%0,%1,%2,%3};"
        : "+f"(c[0]), "+f"(c[1]), "+f"(c[2]), "+f"(c[3])
        : "r"(a.x), "r"(a.y), "r"(a.z), "r"(a.w), "r"(b0), "r"(b1));
}

__device__ __forceinline__ uint4 ldsm4(uint32_t addr) {
    uint4 v;
    asm volatile("ldmatrix.sync.aligned.m8n8.x4.shared.b16 {%0,%1,%2,%3}, [%4];"
                 : "=r"(v.x), "=r"(v.y), "=r"(v.z), "=r"(v.w) : "r"(addr));
    return v;
}

__device__ __forceinline__ uint32_t smem_u32(const void* p) {
    uint32_t a;
    asm("{ .reg .u64 t; cvta.to.shared.u64 t, %1; cvt.u32.u64 %0, t; }" : "=r"(a) : "l"(p));
    return a;
}

// ---------------- main kernel: 512 thr, 4x4 warps of 64p x 32d, 1 CTA/SM ----------------
__global__ __launch_bounds__(512, 1)
void encoder_hmma_kernel(const float* __restrict__ x,
                         const float* __restrict__ ts,
                         const float* __restrict__ bias,
                         float* __restrict__ out) {
    extern __shared__ char smem[];
    const int tid  = threadIdx.x;
    const int lane = tid & 31;
    const int wid  = tid >> 5;     // 0..15
    const int wm   = wid >> 2;     // 0..3  (64 p rows each)
    const int wn   = wid & 3;      // 0..3  (32 d cols each)
    const int t    = lane & 3;
    const int g    = lane >> 2;
    const int p0   = blockIdx.x * 256;
    const int b    = blockIdx.y;

    float* smed = (float*)(smem + OFF_SMED);
    float* cb   = (float*)(smem + OFF_CB);
    const char* xbc = (const char*)(x + (size_t)b * (L_ * 32));

    const uint32_t smemB = smem_u32(smem) + OFF_B;
    const uint32_t smemA = smem_u32(smem) + OFF_A + wm * 8192;   // group-private (2 bufs x 4KB)

    // ---- fill ALL of B once (128KB; 256B per thread) ----
    {
        uint32_t dst = smemB + tid * 16;
        const uint4* srcp = (const uint4*)g_Bh + tid;
        #pragma unroll
        for (int i = 0; i < 16; i++) {
            asm volatile("cp.async.ca.shared.global [%0], [%1], 16;"
                         :: "r"(dst + i * 8192), "l"(srcp + i * 512));
        }
        asm volatile("cp.async.commit_group;");
    }

    // ---- bias + medians (one p-row per thread, 256 rows) ----
    if (tid < 128) cb[tid] = bias[tid];
    if (tid < 256) {
        int p = p0 + tid;
        float med = 0.f;
        if (p < P_) {
            float v[KW];
            const float* tp = ts + b * L_ + p * STRIDE_;
            #pragma unroll
            for (int i = 0; i < KW; i++) v[i] = tp[i];
            #pragma unroll
            for (int pass = 0; pass < KW; pass++) {
                int st = pass & 1;
                #pragma unroll
                for (int i = 0; i < KW - 1; i++) {
                    if ((i & 1) == st) {
                        float lo = fminf(v[i], v[i + 1]);
                        float hi = fmaxf(v[i], v[i + 1]);
                        v[i] = lo; v[i + 1] = hi;
                    }
                }
            }
            med = v[(KW - 1) / 2];
        }
        smed[tid] = med;
    }

    // ---- A staging addressing (group-local: 128 threads stage 64 rows x 32k) ----
    const int gt  = tid & 127;
    const int r0p = gt >> 3;        // 0..15
    const int j   = gt & 7;
    uint32_t offA[4];     // byte offset into xbc (chunk adds ci*128); rows r0p + 16i
    #pragma unroll
    for (int i = 0; i < 4; i++) {
        int p = p0 + wm * 64 + r0p + 16 * i;
        offA[i] = (p < P_) ? ((uint32_t)p * 1024u + (uint32_t)j * 16u) : ((uint32_t)j * 16u);
    }
    const uint32_t sts_base = (uint32_t)(r0p * 64 + (j >> 1) * 16);
    const uint32_t sts_lo   = (uint32_t)((j & 1) * 8);

    // ---- LDSM source offsets (local rows 0..63) ----
    uint32_t lds_off[2][4];
    {
        int row_l = (lane & 7) + (lane & 8);
        int cbyt  = (lane >> 4) << 4;
        #pragma unroll
        for (int ks = 0; ks < 2; ks++)
            #pragma unroll
            for (int mt = 0; mt < 4; mt++)
                lds_off[ks][mt] = SWZ((uint32_t)((row_l + mt * 16) * 64 + cbyt + ks * 32));
    }

    float4 xa[4];
    #define LOAD_X(CI) do {                                                   \
        _Pragma("unroll")                                                     \
        for (int i = 0; i < 4; i++)                                           \
            xa[i] = *(const float4*)(xbc + offA[i] + (CI) * 128);             \
    } while (0)

    #define STS_A(BUF) do {                                                   \
        uint32_t sb = smemA + (BUF) * 4096;                                   \
        _Pragma("unroll")                                                     \
        for (int i = 0; i < 4; i++) {                                         \
            __half2 h0 = __floats2half2_rn(xa[i].x, xa[i].y);                 \
            __half2 h1 = __floats2half2_rn(xa[i].z, xa[i].w);                 \
            uint32_t ad = SWZ(sts_base + (uint32_t)(i * 1024)) + sts_lo;      \
            asm volatile("st.shared.v2.b32 [%0], {%1, %2};"                   \
                :: "r"(sb + ad), "r"(*(uint32_t*)&h0), "r"(*(uint32_t*)&h1)); \
        }                                                                     \
    } while (0)

    // group barrier: 4 warps (128 threads), id = wm+1
    #define BARG() asm volatile("bar.sync %0, 128;" :: "r"(wm + 1) : "memory")

    float acc[4][4][4];
    #pragma unroll
    for (int i = 0; i < 4; i++)
        #pragma unroll
        for (int jj = 0; jj < 4; jj++)
            #pragma unroll
            for (int q = 0; q < 4; q++) acc[i][jj][q] = 0.f;

    const uint4* Bs = (const uint4*)(smem + OFF_B);

    #define COMPUTE(BUF, CI) do {                                             \
        uint32_t abase = smemA + (BUF) * 4096;                                \
        _Pragma("unroll")                                                     \
        for (int ks = 0; ks < 2; ks++) {                                      \
            const uint4* brow = Bs + ((CI) * 2 + ks) * 256 + wn * 64 + lane;  \
            uint4 bb0 = brow[0];                                              \
            uint4 bb1 = brow[32];                                             \
            uint4 af[4];                                                      \
            _Pragma("unroll")                                                 \
            for (int mt = 0; mt < 4; mt++) af[mt] = ldsm4(abase + lds_off[ks][mt]); \
            _Pragma("unroll")                                                 \
            for (int mt = 0; mt < 4; mt++) {                                  \
                mma_f16(acc[mt][0], af[mt], bb0.x, bb0.y);                    \
                mma_f16(acc[mt][1], af[mt], bb0.z, bb0.w);                    \
                mma_f16(acc[mt][2], af[mt], bb1.x, bb1.y);                    \
                mma_f16(acc[mt][3], af[mt], bb1.z, bb1.w);                    \
            }                                                                 \
        }                                                                     \
    } while (0)

    // ---- prologue: stage chunks 0,1; chunk 2 in regs ----
    LOAD_X(0);
    STS_A(0);
    LOAD_X(1);
    STS_A(1);
    LOAD_X(2);
    asm volatile("cp.async.wait_group 0;" ::: "memory");
    __syncthreads();     // B + A bufs + medians visible (ONLY CTA-wide sync)

    // ---- main loop: group barriers only; tail BARG closes the staging race ----
    #pragma unroll 2
    for (int ci = 0; ci < NCH; ci++) {
        COMPUTE(ci & 1, ci);
        if (ci + 2 < NCH) {
            BARG();                        // group done reading buf (ci&1)
            STS_A(ci & 1);                 // stage chunk ci+2
            if (ci + 3 < NCH) LOAD_X(ci + 3);
        } else if (ci + 2 == NCH) {
            BARG();                        // order partner warps' last STS_A
        }
    }

    // ---- epilogue: bias + sinusoidal PE from median ----
    {
        float dt[4];
        #pragma unroll
        for (int nt = 0; nt < 4; nt++) {
            int i = wn * 16 + nt * 4 + t;                // d0/2
            dt[nt] = __expf((float)i * -0.14391156831f); // -2*ln(10000)/128
        }
        #pragma unroll
        for (int mt = 0; mt < 4; mt++) {
            #pragma unroll
            for (int half = 0; half < 2; half++) {
                int prow = wm * 64 + mt * 16 + g + half * 8;
                int p = p0 + prow;
                if (p >= P_) continue;
                float med = smed[prow];
                float* orow = out + ((size_t)b * P_ + p) * D_;
                #pragma unroll
                for (int nt = 0; nt < 4; nt++) {
                    int d0 = wn * 32 + nt * 8 + 2 * t;
                    float sn, cs;
                    __sincosf(med * dt[nt], &sn, &cs);
                    float2 o;
                    o.x = acc[mt][nt][half * 2 + 0] + cb[d0] + sn;
                    o.y = acc[mt][nt][half * 2 + 1] + cb[d0 + 1] + cs;
                    *(float2*)(orow + d0) = o;
                }
            }
        }
    }
}

extern "C" void kernel_launch(void* const* d_in, const int* in_sizes, int n_in,
                              void* d_out, int out_size) {
    const float* x    = (const float*)d_in[0];
    const float* ts   = (const float*)d_in[1];
    const float* w    = (const float*)d_in[2];
    const float* bias = (const float*)d_in[3];
    float* out = (float*)d_out;

    prep_w_kernel<<<128, 256>>>(w);

    cudaFuncSetAttribute(encoder_hmma_kernel,
                         cudaFuncAttributeMaxDynamicSharedMemorySize, SM_TOTAL);
    dim3 grid(16, B_);
    encoder_hmma_kernel<<<grid, 512, SM_TOTAL>>>(x, ts, bias, out);
}